// round 6
// baseline (speedup 1.0000x reference)
#include <cuda_runtime.h>
#include <cstdint>

#define DEVINL __device__ __forceinline__

static constexpr int IN_F   = 256;
static constexpr int OUT_F  = 64;
static constexpr int M_TILE = 128;
static constexpr int NCHUNK = 64;      // K chunks of 64 (4 inputs x 16 slots)

// smem layout (bytes, from 1024-aligned dynamic base)
static constexpr int SM_X    = 0;                 // x panel: 16 cols x 130 pitch = 8320B
static constexpr int SM_A    = 9216;              // A frags: 32KB (1024-aligned)
static constexpr int SM_B    = SM_A + 32768;      // B frags: 16KB (41984)
static constexpr int SMEM_SZ = SM_B + 16384 + 1024; // + align slack

__device__ float g_B[NCHUNK * 4096];   // 1MB pre-fragmented tf32 weights

DEVINL uint32_t smem_u32(const void* p) {
    uint32_t a;
    asm("{ .reg .u64 t; cvta.to.shared.u64 t, %1; cvt.u32.u64 %0, t; }" : "=r"(a) : "l"(p));
    return a;
}
DEVINL uint32_t to_tf32(float f) {
    uint32_t u; asm("cvt.rna.tf32.f32 %0, %1;" : "=r"(u) : "f"(f)); return u;
}
DEVINL void sts128(uint32_t a, uint32_t x, uint32_t y, uint32_t z, uint32_t w) {
    asm volatile("st.shared.v4.b32 [%0], {%1,%2,%3,%4};" :: "r"(a), "r"(x), "r"(y), "r"(z), "r"(w) : "memory");
}
DEVINL void sts32(uint32_t a, uint32_t v) {
    asm volatile("st.shared.b32 [%0], %1;" :: "r"(a), "r"(v) : "memory");
}
DEVINL float lds32f(uint32_t a) {
    float v; asm volatile("ld.shared.f32 %0, [%1];" : "=f"(v) : "r"(a)); return v;
}
DEVINL void lds128(uint32_t a, uint32_t& x, uint32_t& y, uint32_t& z, uint32_t& w) {
    asm volatile("ld.shared.v4.b32 {%0,%1,%2,%3}, [%4];" : "=r"(x), "=r"(y), "=r"(z), "=r"(w) : "r"(a));
}
DEVINL void lds64(uint32_t a, uint32_t& x, uint32_t& y) {
    asm volatile("ld.shared.v2.b32 {%0,%1}, [%2];" : "=r"(x), "=r"(y) : "r"(a));
}
DEVINL void mma8(float* d, const uint32_t* A, uint32_t b0, uint32_t b1) {
    asm volatile(
        "mma.sync.aligned.m16n8k8.row.col.f32.tf32.tf32.f32 "
        "{%0,%1,%2,%3}, {%4,%5,%6,%7}, {%8,%9}, {%0,%1,%2,%3};"
        : "+f"(d[0]), "+f"(d[1]), "+f"(d[2]), "+f"(d[3])
        : "r"(A[0]), "r"(A[1]), "r"(A[2]), "r"(A[3]), "r"(b0), "r"(b1));
}
DEVINL uint32_t sw128(uint32_t o) { return o ^ ((o >> 3) & 0x70u); }

// ---- pre-kernel: weights -> tf32 B fragments ----
// layout: [chunk][q(0..7)][nb(0..7)][lane(0..31)][reg(0..1)]
// b0 = B[k = lane&3][n = nb*8 + lane>>2], b1 = k+4   (k within q-block)
__global__ void kan_expand(const float* __restrict__ bw, const float* __restrict__ sw) {
    int fi = blockIdx.x * 256 + threadIdx.x;     // 0 .. 262143
    int r    = fi & 4095;
    int reg  = r & 1;
    int lane = (r >> 1) & 31;
    int nb   = (r >> 6) & 7;
    int q    = (r >> 9) & 7;
    int c    = fi >> 12;
    int kloc = q * 8 + (lane & 3) + reg * 4;     // 0..63 within chunk
    int isub = kloc >> 4, slot = kloc & 15;
    int i = c * 4 + isub;
    int o = nb * 8 + (lane >> 2);
    float v = 0.0f;
    if (slot == 0)       v = bw[o * IN_F + i];
    else if (slot <= 13) v = sw[(o * IN_F + i) * 13 + (slot - 1)];
    g_B[fi] = __uint_as_float(to_tf32(v));
}

// ---- main kernel ----
__global__ void __launch_bounds__(256, 2)
kan_main(const float* __restrict__ x, float* __restrict__ out) {
    extern __shared__ char smem_raw[];
    const uint32_t sb = (smem_u32(smem_raw) + 1023u) & ~1023u;
    const int tid = threadIdx.x, wid = tid >> 5, lane = tid & 31;
    // producer ids: tid = mb*32 + isub*8 + g
    const int mb_p = tid >> 5, isub_p = (tid >> 3) & 3, g_p = tid & 7;
    // consumer ids: warp = K-group gw, m-slice wg (rows wg*32..+32)
    const int gw = wid >> 2, wg = wid & 3;
    const int rowBase = blockIdx.x * M_TILE;

    float acc[2][8][4];
    #pragma unroll
    for (int a = 0; a < 2; ++a)
        #pragma unroll
        for (int b = 0; b < 8; ++b)
            #pragma unroll
            for (int k = 0; k < 4; ++k) acc[a][b][k] = 0.0f;

    for (int c = 0; c < NCHUNK; ++c) {
        if ((c & 3) == 0) {   // refresh x panel: 16 global cols, transposed, pitch 130
            #pragma unroll
            for (int u = 0; u < 2; ++u) {
                int v = tid + 256 * u;           // 512 float4 slots
                int pr = v >> 2, q4 = v & 3;
                const float4 xv = *reinterpret_cast<const float4*>(
                    x + (size_t)(rowBase + pr) * IN_F + c * 4 + 4 * q4);
                uint32_t a0 = sb + SM_X + (uint32_t)((4 * q4) * 130 + pr) * 4u;
                sts32(a0,                __float_as_uint(xv.x));
                sts32(a0 + 130u * 4u,    __float_as_uint(xv.y));
                sts32(a0 + 260u * 4u,    __float_as_uint(xv.z));
                sts32(a0 + 390u * 4u,    __float_as_uint(xv.w));
            }
            __syncthreads();
        }

        // stage B chunk (pre-fragmented; linear copy)
        {
            const float4* src = reinterpret_cast<const float4*>(g_B + c * 4096);
            #pragma unroll
            for (int u = 0; u < 4; ++u) {
                int v = tid + 256 * u;           // 1024 float4
                float4 w = src[v];
                sts128(sb + SM_B + (uint32_t)v * 16u,
                       __float_as_uint(w.x), __float_as_uint(w.y),
                       __float_as_uint(w.z), __float_as_uint(w.w));
            }
        }

        // produce A fragments for (rows r0=mb*16+g, r1=r0+8, input isub)
        {
            const uint32_t xcol = sb + SM_X + (uint32_t)(((c & 3) * 4 + isub_p) * 130) * 4u;
            const float xv0 = lds32f(xcol + (uint32_t)(mb_p * 16 + g_p) * 4u);
            const float xv1 = lds32f(xcol + (uint32_t)(mb_p * 16 + g_p + 8) * 4u);

            uint32_t silu[2], bt[2][4]; int mm[2];
            #pragma unroll
            for (int rr = 0; rr < 2; ++rr) {
                const float xv = rr ? xv1 : xv0;
                silu[rr] = to_tf32(__fdividef(xv, 1.0f + __expf(-xv)));
                const float xc = fminf(fmaxf(xv, -2.5f), 2.5f);
                const float u  = (xc + 3.2f) * 2.5f;
                const float mf = floorf(u);
                mm[rr] = (int)mf;
                const float t = u - mf, t2 = t * t, t3 = t2 * t, omt = 1.0f - t;
                const float i6 = 1.0f / 6.0f;
                bt[rr][0] = to_tf32(i6 * omt * omt * omt);
                bt[rr][1] = to_tf32(i6 * (3.0f * t3 - 6.0f * t2 + 4.0f));
                bt[rr][2] = to_tf32(i6 * (-3.0f * t3 + 3.0f * t2 + 3.0f * t + 1.0f));
                bt[rr][3] = to_tf32(i6 * t3);
            }
            // value at slot s (0..15): s==0 -> silu; tap iff sidx=s+2-m in [0,3] and s<=13
            #pragma unroll
            for (int h = 0; h < 2; ++h) {        // q = 2*isub + h, slots 8h..8h+7
                const int q = 2 * isub_p + h;
                uint32_t v[2][2][4];             // [row][k-half][t]
                #pragma unroll
                for (int rr = 0; rr < 2; ++rr) {
                    const int m = mm[rr];
                    #pragma unroll
                    for (int t = 0; t < 4; ++t) {
                        const int k0 = (t + 2 - m) & 3;
                        const uint32_t bsel =
                            k0 == 0 ? bt[rr][0] : k0 == 1 ? bt[rr][1] :
                            k0 == 2 ? bt[rr][2] : bt[rr][3];
                        #pragma unroll
                        for (int ph = 0; ph < 2; ++ph) {
                            const int s = 8 * h + t + 4 * ph;
                            const int sidx = s + 2 - m;
                            uint32_t val = ((unsigned)sidx <= 3u && s <= 13) ? bsel : 0u;
                            if (s == 0) val = silu[rr];
                            v[rr][ph][t] = val;
                        }
                    }
                }
                #pragma unroll
                for (int t = 0; t < 4; ++t) {
                    const uint32_t off = (uint32_t)(((mb_p * 8 + q) * 32 + g_p * 4 + t)) * 16u;
                    sts128(sb + SM_A + sw128(off),
                           v[0][0][t], v[1][0][t], v[0][1][t], v[1][1][t]);
                }
            }
        }

        __syncthreads();

        if (gw == (c & 1)) {     // this K-group consumes the chunk
            #pragma unroll
            for (int q = 0; q < 8; ++q) {
                uint32_t A0[4], A1[4];
                lds128(sb + SM_A + sw128((uint32_t)((((2 * wg) * 8 + q) * 32 + lane)) * 16u),
                       A0[0], A0[1], A0[2], A0[3]);
                lds128(sb + SM_A + sw128((uint32_t)((((2 * wg + 1) * 8 + q) * 32 + lane)) * 16u),
                       A1[0], A1[1], A1[2], A1[3]);
                #pragma unroll
                for (int nb = 0; nb < 8; ++nb) {
                    uint32_t b0, b1;
                    lds64(sb + SM_B + (uint32_t)(((q * 8 + nb) * 32 + lane)) * 8u, b0, b1);
                    mma8(acc[0][nb], A0, b0, b1);
                    mma8(acc[1][nb], A1, b0, b1);
                }
            }
        }
        __syncthreads();
    }

    // ---- epilogue: reduce K-groups through smem, then coalesced store ----
    const uint32_t ex = sb + SM_A;   // 128 x 64 fp32 exchange
    if (gw == 1) {
        #pragma unroll
        for (int mbl = 0; mbl < 2; ++mbl)
            #pragma unroll
            for (int nb = 0; nb < 8; ++nb)
                #pragma unroll
                for (int k = 0; k < 4; ++k) {
                    int row = wg * 32 + mbl * 16 + (lane >> 2) + ((k & 2) ? 8 : 0);
                    int col = nb * 8 + (lane & 3) * 2 + (k & 1);
                    sts32(ex + (uint32_t)(row * 64 + col) * 4u,
                          __float_as_uint(acc[mbl][nb][k]));
                }
    }
    __syncthreads();
    if (gw == 0) {
        #pragma unroll
        for (int mbl = 0; mbl < 2; ++mbl)
            #pragma unroll
            for (int nb = 0; nb < 8; ++nb)
                #pragma unroll
                for (int k = 0; k < 4; ++k) {
                    int row = wg * 32 + mbl * 16 + (lane >> 2) + ((k & 2) ? 8 : 0);
                    int col = nb * 8 + (lane & 3) * 2 + (k & 1);
                    uint32_t a = ex + (uint32_t)(row * 64 + col) * 4u;
                    float s = acc[mbl][nb][k] + lds32f(a);
                    sts32(a, __float_as_uint(s));
                }
    }
    __syncthreads();
    #pragma unroll
    for (int u = 0; u < 8; ++u) {
        int idx = tid + 256 * u;                 // 2048 float4
        int row = idx >> 4, c4 = idx & 15;
        uint32_t a = ex + (uint32_t)(row * 64 + c4 * 4) * 4u;
        uint32_t p0, p1, p2, p3;
        lds128(a, p0, p1, p2, p3);
        float4 v;
        v.x = __uint_as_float(p0); v.y = __uint_as_float(p1);
        v.z = __uint_as_float(p2); v.w = __uint_as_float(p3);
        reinterpret_cast<float4*>(out + (size_t)(rowBase + row) * OUT_F)[c4] = v;
    }
}

extern "C" void kernel_launch(void* const* d_in, const int* in_sizes, int n_in,
                              void* d_out, int out_size) {
    const float* x  = (const float*)d_in[0];
    const float* bw = (const float*)d_in[1];
    const float* sw = (const float*)d_in[2];
    float* out = (float*)d_out;
    cudaFuncSetAttribute(kan_main, cudaFuncAttributeMaxDynamicSharedMemorySize, SMEM_SZ);
    kan_expand<<<1024, 256>>>(bw, sw);
    kan_main<<<65536 / M_TILE, 256, SMEM_SZ>>>(x, out);
}